// round 5
// baseline (speedup 1.0000x reference)
#include <cuda_runtime.h>
#include <cstdint>
#include <cstddef>

#define BB 8
#define CC 256
#define NNDIM 1024
#define KDIM 16
#define CQ 64

// ---------------- scratch (device globals; no allocation allowed) ----------------
__device__ float g_wcat[384 * 256];                         // concat q/k/v weights
__device__ float g_xT[(size_t)BB * KDIM * CC * NNDIM];      // [b][k][c][n]  134MB
__device__ float g_xq[(size_t)BB * KDIM * CQ * NNDIM];      // [b][k][cq][n]
__device__ float g_xk[(size_t)BB * KDIM * CQ * NNDIM];      // [b][k][cq][n]
__device__ float g_xv[(size_t)BB * KDIM * CC * NNDIM];      // [b][k][c][n]
__device__ float g_S [(size_t)BB * KDIM * NNDIM * NNDIM];   // S^T probs [z][m][n] 536MB
__device__ float g_d [(size_t)BB * KDIM * CC * NNDIM];      // x - x_r, [b][k][c][n]
__device__ float g_t [(size_t)BB * CC * KDIM * NNDIM];      // t proj, [b][c][k][n]
__device__ float g_a [CC];
__device__ float g_b2[CC];

__device__ __forceinline__ uint32_t f2tf32(float f) {
    uint32_t u;
    asm("cvt.rna.tf32.f32 %0, %1;" : "=r"(u) : "f"(f));
    return u;
}
__device__ __forceinline__ void split_tf32(float x, uint32_t& hi, uint32_t& lo) {
    asm("cvt.rna.tf32.f32 %0, %1;" : "=r"(hi) : "f"(x));
    float hf = __uint_as_float(hi);
    asm("cvt.rna.tf32.f32 %0, %1;" : "=r"(lo) : "f"(x - hf));
}

__device__ __forceinline__ void mma_tf32(float c[4], const uint32_t a[4], const uint32_t b[2]) {
    asm volatile("mma.sync.aligned.m16n8k8.row.col.f32.tf32.tf32.f32 "
                 "{%0,%1,%2,%3}, {%4,%5,%6,%7}, {%8,%9}, {%0,%1,%2,%3};"
                 : "+f"(c[0]), "+f"(c[1]), "+f"(c[2]), "+f"(c[3])
                 : "r"(a[0]), "r"(a[1]), "r"(a[2]), "r"(a[3]), "r"(b[0]), "r"(b[1]));
}

// ---------------- kernel 0: concat weights ----------------
__global__ void k_concat(const float* __restrict__ q_w, const float* __restrict__ k_w,
                         const float* __restrict__ v_w) {
    int i = blockIdx.x * 256 + threadIdx.x;
    if (i >= 384 * 256) return;
    int o = i >> 8;
    float v;
    if (o < 64)        v = q_w[i];
    else if (o < 128)  v = k_w[i - 64 * 256];
    else               v = v_w[i - 128 * 256];
    g_wcat[i] = v;
}

// ---------------- kernel 1: transpose x [b,c,n,k] -> xT [b,k,c,n] ----------------
__global__ void k_transpose_x(const float* __restrict__ x) {
    __shared__ float ts[16][68];
    int bc = blockIdx.x;
    int b = bc >> 8, c = bc & 255;
    int t = threadIdx.x;
    int nn = t >> 2, kg = (t & 3) << 2;
    int kk = t >> 4, n4 = (t & 15) << 2;
    for (int n0 = 0; n0 < NNDIM; n0 += 64) {
        float4 v = *(const float4*)&x[(((size_t)bc * NNDIM) + n0 + nn) * KDIM + kg];
        ts[kg + 0][nn] = v.x; ts[kg + 1][nn] = v.y; ts[kg + 2][nn] = v.z; ts[kg + 3][nn] = v.w;
        __syncthreads();
        float4 o = make_float4(ts[kk][n4], ts[kk][n4 + 1], ts[kk][n4 + 2], ts[kk][n4 + 3]);
        *(float4*)&g_xT[(((size_t)(b * KDIM + kk) * CC + c) * NNDIM) + n0 + n4] = o;
        __syncthreads();
    }
}

// ---------------- unified tf32 mma.sync tile GEMM (proj / xr / tproj) ----------------
template<int MODE>
__global__ __launch_bounds__(256) void k_mma(const float* __restrict__ A_ext,
                                             const float* __restrict__ bias) {
    __shared__ uint32_t As[128][36];
    __shared__ uint32_t Bs[128][36];

    const int t = threadIdx.x;
    const int wid = t >> 5, lane = t & 31;
    const int gr = lane >> 2, tg = lane & 3;
    const int wm = (wid >> 2) * 64, wn = (wid & 3) * 32;
    const int z  = blockIdx.z;
    const int n0 = blockIdx.x << 7;
    const int m0 = blockIdx.y << 7;
    const int KTOT = (MODE == 0) ? 1024 : 256;
    const int NC = KTOT / 32;

    const float* Ap;
    const float* Bp;
    if (MODE == 0) {
        Ap = g_xv + ((size_t)z * CC + m0) * NNDIM;
        Bp = g_S + (size_t)z * NNDIM * NNDIM + (size_t)n0 * NNDIM;
    } else if (MODE == 1) {
        Ap = g_wcat + (size_t)m0 * 256;
        Bp = g_xT + (size_t)z * CC * NNDIM + n0;
    } else {
        Ap = A_ext + (size_t)m0 * 256;
        Bp = g_d + (size_t)z * CC * NNDIM + n0;
    }
    const int lda = (MODE == 0) ? NNDIM : 256;

    float ra[16], rb[16];
    const int arow = t >> 1, ah = (t & 1) << 4;
    const int bc_ = t >> 3, bn4 = (t & 7) << 4;

    auto loadA = [&](int k0) {
#pragma unroll
        for (int j = 0; j < 4; j++) {
            float4 v = *(const float4*)&Ap[(size_t)arow * lda + k0 + ah + j * 4];
            ra[j * 4 + 0] = v.x; ra[j * 4 + 1] = v.y; ra[j * 4 + 2] = v.z; ra[j * 4 + 3] = v.w;
        }
    };
    auto loadB = [&](int k0) {
        if (MODE == 0) {
#pragma unroll
            for (int j = 0; j < 4; j++) {
                float4 v = *(const float4*)&Bp[(size_t)arow * NNDIM + k0 + ah + j * 4];
                rb[j * 4 + 0] = v.x; rb[j * 4 + 1] = v.y; rb[j * 4 + 2] = v.z; rb[j * 4 + 3] = v.w;
            }
        } else {
#pragma unroll
            for (int j = 0; j < 4; j++) {
                float4 v = *(const float4*)&Bp[(size_t)(k0 + bc_) * NNDIM + bn4 + j * 4];
                rb[j * 4 + 0] = v.x; rb[j * 4 + 1] = v.y; rb[j * 4 + 2] = v.z; rb[j * 4 + 3] = v.w;
            }
        }
    };
    auto storeAB = [&]() {
#pragma unroll
        for (int j = 0; j < 16; j++) As[arow][ah + j] = f2tf32(ra[j]);
        if (MODE == 0) {
#pragma unroll
            for (int j = 0; j < 16; j++) Bs[arow][ah + j] = f2tf32(rb[j]);
        } else {
#pragma unroll
            for (int j = 0; j < 16; j++) Bs[bn4 + j][bc_] = f2tf32(rb[j]);
        }
    };

    float acc[4][4][4] = {};
    loadA(0); loadB(0);
    for (int c = 0; c < NC; c++) {
        __syncthreads();
        storeAB();
        __syncthreads();
        if (c + 1 < NC) { loadA((c + 1) * 32); loadB((c + 1) * 32); }
#pragma unroll
        for (int ks = 0; ks < 4; ks++) {
            int k0 = ks * 8;
            uint32_t af[4][4], bf[4][2];
#pragma unroll
            for (int mt = 0; mt < 4; mt++) {
                int r = wm + mt * 16 + gr;
                af[mt][0] = As[r][k0 + tg];
                af[mt][1] = As[r + 8][k0 + tg];
                af[mt][2] = As[r][k0 + tg + 4];
                af[mt][3] = As[r + 8][k0 + tg + 4];
            }
#pragma unroll
            for (int nt = 0; nt < 4; nt++) {
                int r = wn + nt * 8 + gr;
                bf[nt][0] = Bs[r][k0 + tg];
                bf[nt][1] = Bs[r][k0 + tg + 4];
            }
#pragma unroll
            for (int mt = 0; mt < 4; mt++)
#pragma unroll
                for (int nt = 0; nt < 4; nt++)
                    mma_tf32(acc[mt][nt], af[mt], bf[nt]);
        }
    }

#pragma unroll
    for (int mt = 0; mt < 4; mt++) {
#pragma unroll
        for (int nt = 0; nt < 4; nt++) {
#pragma unroll
            for (int h = 0; h < 2; h++) {
                int row = m0 + wm + mt * 16 + gr + h * 8;
                int col = n0 + wn + nt * 8 + 2 * tg;
                float v0 = acc[mt][nt][h * 2 + 0];
                float v1 = acc[mt][nt][h * 2 + 1];
                if (MODE == 0) {
                    size_t idx = ((size_t)z * CC + row) * NNDIM + col;
                    float2 xv = *(const float2*)&g_xT[idx];
                    float2 o = make_float2(xv.x - v0, xv.y - v1);
                    *(float2*)&g_d[idx] = o;
                } else if (MODE == 1) {
                    if (row < 64) {
                        *(float2*)&g_xq[((size_t)z * CQ + row) * NNDIM + col] = make_float2(v0, v1);
                    } else if (row < 128) {
                        *(float2*)&g_xk[((size_t)z * CQ + row - 64) * NNDIM + col] = make_float2(v0, v1);
                    } else {
                        float bb = bias[row - 128];
                        *(float2*)&g_xv[((size_t)z * CC + row - 128) * NNDIM + col] =
                            make_float2(v0 + bb, v1 + bb);
                    }
                } else {
                    float bb = bias[row];
                    int b = z >> 4, kb = z & 15;
                    *(float2*)&g_t[(((size_t)(b * CC + row)) * KDIM + kb) * NNDIM + col] =
                        make_float2(v0 + bb, v1 + bb);
                }
            }
        }
    }
}

// ---------------- kernel 3: energy (split-tf32 mma) + softmax, writes S^T [z][m][n] ----------------
// Block: 16 Q-rows (n0..n0+15) x full 1024 m. 8 warps, warp w owns m in [w*128, w*128+128).
// E = Qhi*Khi + Qhi*Klo + Qlo*Khi  (fp32-accurate). K streamed in 8-col slices through smem.
#define ES 1028
#define QH_OFF (16 * ES)            // q hi [16][68]
#define QL_OFF (QH_OFF + 16 * 68)   // q lo [16][68]
#define KH_OFF (QL_OFF + 16 * 68)   // k hi [8][1032]
#define KL_OFF (KH_OFF + 8 * 1032)  // k lo [8][1032]
#define SMEM_E ((KL_OFF + 8 * 1032) * 4)
__global__ __launch_bounds__(256) void k_energy_mma() {
    extern __shared__ float sh[];
    float* e_s = sh;
    float* q_h = sh + QH_OFF;
    float* q_l = sh + QL_OFF;
    float* k_h = sh + KH_OFF;
    float* k_l = sh + KL_OFF;
    int z  = blockIdx.y;
    int n0 = blockIdx.x << 4;
    int t  = threadIdx.x;
    int wid = t >> 5, lane = t & 31;
    int gr = lane >> 2, tg = lane & 3;
    const float* qg = g_xq + (size_t)z * CQ * NNDIM;
    const float* kg = g_xk + (size_t)z * CQ * NNDIM;

    // load Q tile [64 cq][16 n] -> q_h/q_l [n][cq], stride 68
    {
        int cc = t >> 2, nn = (t & 3) << 2;
        float4 v = *(const float4*)&qg[(size_t)cc * NNDIM + n0 + nn];
        float f[4] = {v.x, v.y, v.z, v.w};
#pragma unroll
        for (int j = 0; j < 4; j++) {
            uint32_t h, l;
            split_tf32(f[j], h, l);
            q_h[(nn + j) * 68 + cc] = __uint_as_float(h);
            q_l[(nn + j) * 68 + cc] = __uint_as_float(l);
        }
    }

    float acc[16][4] = {};
    for (int ks = 0; ks < 8; ks++) {
        int k8 = ks << 3;
        __syncthreads();   // previous slice fully consumed (also orders q_s stores on ks=0)
        // stream K slice: rows k8..k8+7, all 1024 m
#pragma unroll
        for (int i = 0; i < 8; i++) {
            float4 v = *(const float4*)&kg[(size_t)(k8 + i) * NNDIM + (t << 2)];
            float4 h4, l4;
            uint32_t h, l;
            split_tf32(v.x, h, l); h4.x = __uint_as_float(h); l4.x = __uint_as_float(l);
            split_tf32(v.y, h, l); h4.y = __uint_as_float(h); l4.y = __uint_as_float(l);
            split_tf32(v.z, h, l); h4.z = __uint_as_float(h); l4.z = __uint_as_float(l);
            split_tf32(v.w, h, l); h4.w = __uint_as_float(h); l4.w = __uint_as_float(l);
            *(float4*)&k_h[i * 1032 + (t << 2)] = h4;
            *(float4*)&k_l[i * 1032 + (t << 2)] = l4;
        }
        __syncthreads();
        uint32_t ah[4], al[4];
        ah[0] = __float_as_uint(q_h[gr * 68 + k8 + tg]);
        ah[1] = __float_as_uint(q_h[(gr + 8) * 68 + k8 + tg]);
        ah[2] = __float_as_uint(q_h[gr * 68 + k8 + tg + 4]);
        ah[3] = __float_as_uint(q_h[(gr + 8) * 68 + k8 + tg + 4]);
        al[0] = __float_as_uint(q_l[gr * 68 + k8 + tg]);
        al[1] = __float_as_uint(q_l[(gr + 8) * 68 + k8 + tg]);
        al[2] = __float_as_uint(q_l[gr * 68 + k8 + tg + 4]);
        al[3] = __float_as_uint(q_l[(gr + 8) * 68 + k8 + tg + 4]);
#pragma unroll
        for (int nf = 0; nf < 16; nf++) {
            int m = wid * 128 + nf * 8 + gr;
            uint32_t bh[2], bl[2];
            bh[0] = __float_as_uint(k_h[tg * 1032 + m]);
            bh[1] = __float_as_uint(k_h[(tg + 4) * 1032 + m]);
            bl[0] = __float_as_uint(k_l[tg * 1032 + m]);
            bl[1] = __float_as_uint(k_l[(tg + 4) * 1032 + m]);
            mma_tf32(acc[nf], ah, bh);
            mma_tf32(acc[nf], ah, bl);
            mma_tf32(acc[nf], al, bh);
        }
    }
    __syncthreads();
    // dump E tile to e_s [16][ES]
#pragma unroll
    for (int nf = 0; nf < 16; nf++) {
        int mb = wid * 128 + nf * 8 + 2 * tg;
        *(float2*)&e_s[gr * ES + mb]       = make_float2(acc[nf][0], acc[nf][1]);
        *(float2*)&e_s[(gr + 8) * ES + mb] = make_float2(acc[nf][2], acc[nf][3]);
    }
    __syncthreads();

    // softmax rows
    int lr = t & 15, rr = t >> 4;
    const unsigned FULL = 0xffffffffu;
    float* row = e_s + rr * ES;
    float mx = -1e30f;
#pragma unroll
    for (int i = 0; i < 16; i++) {
        float4 v = *(float4*)&row[i * 64 + lr * 4];
        mx = fmaxf(mx, fmaxf(fmaxf(v.x, v.y), fmaxf(v.z, v.w)));
    }
    mx = fmaxf(mx, __shfl_xor_sync(FULL, mx, 1));
    mx = fmaxf(mx, __shfl_xor_sync(FULL, mx, 2));
    mx = fmaxf(mx, __shfl_xor_sync(FULL, mx, 4));
    mx = fmaxf(mx, __shfl_xor_sync(FULL, mx, 8));
    float sum = 0.0f;
#pragma unroll
    for (int i = 0; i < 16; i++) {
        float4 v = *(float4*)&row[i * 64 + lr * 4];
        v.x = __expf(v.x - mx); v.y = __expf(v.y - mx);
        v.z = __expf(v.z - mx); v.w = __expf(v.w - mx);
        sum += v.x + v.y + v.z + v.w;
        *(float4*)&row[i * 64 + lr * 4] = v;
    }
    sum += __shfl_xor_sync(FULL, sum, 1);
    sum += __shfl_xor_sync(FULL, sum, 2);
    sum += __shfl_xor_sync(FULL, sum, 4);
    sum += __shfl_xor_sync(FULL, sum, 8);
    float* inv_s = q_h;  // reuse
    if (lr == 0) inv_s[rr] = 1.0f / sum;
    __syncthreads();
    // transposed write: S^T[z][m][n0..n0+15]
    float* Sbase = g_S + (size_t)z * NNDIM * NNDIM;
#pragma unroll
    for (int pass = 0; pass < 4; pass++) {
        int m = pass * 256 + t;
        float* dst = Sbase + (size_t)m * NNDIM + n0;
#pragma unroll
        for (int g = 0; g < 4; g++) {
            float4 o;
            o.x = e_s[(g * 4 + 0) * ES + m] * inv_s[g * 4 + 0];
            o.y = e_s[(g * 4 + 1) * ES + m] * inv_s[g * 4 + 1];
            o.z = e_s[(g * 4 + 2) * ES + m] * inv_s[g * 4 + 2];
            o.w = e_s[(g * 4 + 3) * ES + m] * inv_s[g * 4 + 3];
            *(float4*)&dst[g * 4] = o;
        }
    }
}

// ---------------- kernel 4: cross-K renormalization ----------------
__global__ void k_renorm() {
    size_t p = (size_t)blockIdx.x * 256 + threadIdx.x;
    int m = (int)(p & 255) << 2;
    int n = (int)(p >> 8) & 1023;
    int b = (int)(p >> 18);
    size_t base = (((size_t)b * KDIM) * NNDIM + n) * NNDIM + m;
    const size_t ks = (size_t)NNDIM * NNDIM;
    float4 v[16];
    float4 s = make_float4(1e-9f, 1e-9f, 1e-9f, 1e-9f);
#pragma unroll
    for (int k = 0; k < 16; k++) {
        v[k] = *(const float4*)&g_S[base + (size_t)k * ks];
        s.x += v[k].x; s.y += v[k].y; s.z += v[k].z; s.w += v[k].w;
    }
    float4 inv = make_float4(1.0f / s.x, 1.0f / s.y, 1.0f / s.z, 1.0f / s.w);
#pragma unroll
    for (int k = 0; k < 16; k++) {
        v[k].x *= inv.x; v[k].y *= inv.y; v[k].z *= inv.z; v[k].w *= inv.w;
        *(float4*)&g_S[base + (size_t)k * ks] = v[k];
    }
}

// ---------------- kernel 7: BN stats per channel ----------------
__global__ void k_stats(const float* __restrict__ gamma, const float* __restrict__ beta) {
    int c = blockIdx.x;
    int t = threadIdx.x;
    float s = 0.0f, sq = 0.0f;
    for (int b = 0; b < BB; b++) {
        const float* base = g_t + ((size_t)(b * CC + c)) * KDIM * NNDIM;
        for (int fl = t; fl < 4096; fl += 256) {
            float4 v = *(const float4*)&base[fl * 4];
            s  += v.x + v.y + v.z + v.w;
            sq += v.x * v.x + v.y * v.y + v.z * v.z + v.w * v.w;
        }
    }
    __shared__ float ss[256], sqq[256];
    ss[t] = s; sqq[t] = sq;
    __syncthreads();
    for (int o = 128; o > 0; o >>= 1) {
        if (t < o) { ss[t] += ss[t + o]; sqq[t] += sqq[t + o]; }
        __syncthreads();
    }
    if (t == 0) {
        const float cnt = 131072.0f;
        float mean = ss[0] / cnt;
        float var  = sqq[0] / cnt - mean * mean;
        float rstd = rsqrtf(var + 1e-5f);
        float a = rstd * gamma[c];
        g_a[c]  = a;
        g_b2[c] = beta[c] - mean * a;
    }
}

// ---------------- kernel 8: out = x + relu(t*a + b2), transpose [k][n]->[n][k] ----------------
__global__ void k_final(const float* __restrict__ x, float* __restrict__ out) {
    __shared__ float ts[16][68];
    int bc = blockIdx.x;
    int c  = bc & 255;
    int t  = threadIdx.x;
    float a = g_a[c], b2 = g_b2[c];
    int kk = t >> 4, n4 = (t & 15) << 2;
    int nn = t >> 2, kg = (t & 3) << 2;
    for (int n0 = 0; n0 < NNDIM; n0 += 64) {
        float4 v = *(const float4*)&g_t[((size_t)bc * KDIM + kk) * NNDIM + n0 + n4];
        *(float4*)&ts[kk][n4] = v;
        __syncthreads();
        float4 tv = make_float4(ts[kg][nn], ts[kg + 1][nn], ts[kg + 2][nn], ts[kg + 3][nn]);
        tv.x = fmaxf(tv.x * a + b2, 0.0f);
        tv.y = fmaxf(tv.y * a + b2, 0.0f);
        tv.z = fmaxf(tv.z * a + b2, 0.0f);
        tv.w = fmaxf(tv.w * a + b2, 0.0f);
        size_t idx = ((size_t)bc * NNDIM + n0 + nn) * KDIM + kg;
        float4 xv = *(const float4*)&x[idx];
        tv.x += xv.x; tv.y += xv.y; tv.z += xv.z; tv.w += xv.w;
        *(float4*)&out[idx] = tv;
        __syncthreads();
    }
}

// ---------------- launch ----------------
extern "C" void kernel_launch(void* const* d_in, const int* in_sizes, int n_in,
                              void* d_out, int out_size) {
    const float* x     = (const float*)d_in[0];
    const float* q_w   = (const float*)d_in[1];
    const float* k_w   = (const float*)d_in[2];
    const float* v_w   = (const float*)d_in[3];
    const float* v_b   = (const float*)d_in[4];
    const float* t_w   = (const float*)d_in[5];
    const float* t_b   = (const float*)d_in[6];
    const float* gamma = (const float*)d_in[7];
    const float* beta  = (const float*)d_in[8];
    float* out = (float*)d_out;

    cudaFuncSetAttribute(k_energy_mma, cudaFuncAttributeMaxDynamicSharedMemorySize, SMEM_E);

    k_concat<<<384, 256>>>(q_w, k_w, v_w);
    k_transpose_x<<<BB * CC, 256>>>(x);
    k_mma<1><<<dim3(8, 3, BB * KDIM), 256>>>(nullptr, v_b);     // q/k/v projection
    k_energy_mma<<<dim3(64, BB * KDIM), 256, SMEM_E>>>();       // energy + softmax
    k_renorm<<<8192, 256>>>();
    k_mma<0><<<dim3(8, 2, BB * KDIM), 256>>>(nullptr, nullptr); // x_r + (x - x_r)
    k_mma<2><<<dim3(8, 2, BB * KDIM), 256>>>(t_w, t_b);         // t projection
    k_stats<<<CC, 256>>>(gamma, beta);
    k_final<<<BB * CC, 256>>>(x, out);
}